// round 2
// baseline (speedup 1.0000x reference)
#include <cuda_runtime.h>
#include <cuda_bf16.h>
#include <math.h>

// Problem constants
#define B_   8
#define DTOT 512
#define L_   2048
#define H_   8
#define M_   1024
#define DD   64            // head dim d
#define N_   (B_ * L_)     // 16384 rows per head

// Output layout (flattened fp32 concat of (z_q, vq_loss, indices, new_codebooks))
#define OUT_ZQ   0
#define ZQ_ELEMS (B_ * DTOT * L_)           // 8388608
#define OUT_LOSS (ZQ_ELEMS)                 // 8388608 (1 elem)
#define OUT_IDX  (ZQ_ELEMS + 1)             // 8388609
#define IDX_ELEMS (B_ * H_ * L_)            // 131072
#define OUT_NCB  (OUT_IDX + IDX_ELEMS)      // 8519681
#define NCB_ELEMS (H_ * M_ * DD)            // 524288

#define EPS_RMS 1.1920929e-07f
#define COS_EPS 1e-8f
#define DECAY   0.99f

typedef unsigned long long u64;

__device__ __forceinline__ void fma2(u64& d, u64 a, u64 b) {
    asm("fma.rn.f32x2 %0, %1, %2, %3;" : "=l"(d) : "l"(a), "l"(b), "l"(d));
}
__device__ __forceinline__ float2 unpack2(u64 v) {
    float2 r;
    asm("mov.b64 {%0,%1}, %2;" : "=f"(r.x), "=f"(r.y) : "l"(v));
    return r;
}

// Scratch (no allocations allowed -> __device__ globals)
__device__ float g_sums[H_ * M_ * DD];   // segment sums  [H,M,d]
__device__ float g_counts[H_ * M_];      // segment counts [H,M]
__device__ float g_loss;                 // sum of (z - z_q)^2

// ---------------------------------------------------------------------------
// Kernel 0: zero scratch accumulators (graph replays must start clean)
// ---------------------------------------------------------------------------
__global__ void vq_zero_kernel() {
    int i = blockIdx.x * blockDim.x + threadIdx.x;
    if (i < H_ * M_ * DD) g_sums[i] = 0.0f;
    int j = i - H_ * M_ * DD;
    if (j >= 0 && j < H_ * M_) g_counts[j] = 0.0f;
    if (i == H_ * M_ * DD + H_ * M_) g_loss = 0.0f;
}

// ---------------------------------------------------------------------------
// Kernel 1: per-tile argmax over codebook + fused epilogue
//   grid = H_ * 256 blocks (each block: one head, 64 consecutive n)
//   block = 256 threads, 4x4 register blocking over (n, m), packed f32x2 FMA
// ---------------------------------------------------------------------------
__global__ __launch_bounds__(256)
void vq_main_kernel(const float* __restrict__ z,
                    const float* __restrict__ cbk,
                    float* __restrict__ out) {
    __shared__ float Zs[64 * 64];           // [k][n]  n-major (natural n-pairs)
    __shared__ float Cs2[64 * 128];         // [k][2*m] duplicated pairs (b,b)

    const int tid = threadIdx.x;
    const int tx = tid & 15;               // n-group (4 n each)
    const int ty = tid >> 4;               // m-group (4 m each, per chunk)

    const int tile = blockIdx.x;
    const int h  = tile >> 8;              // head
    const int t2 = tile & 255;
    const int n0 = t2 << 6;                // within-head row offset (64 rows)
    const int b  = n0 >> 11;               // n = b*L + l ; tile never crosses b
    const int l0 = n0 & 2047;

    // ---- load Z tile: Zs[j][li] = z[b, h*64+j, l0+li] ----
    {
        const float* zbase = z + ((b * DTOT + h * DD) * L_ + l0);
        #pragma unroll
        for (int i = 0; i < 4; i++) {
            int s = tid + i * 256;          // 1024 float4 slots
            int j = s >> 4;
            int c = (s & 15) << 2;
            float4 v = *(const float4*)(zbase + j * L_ + c);
            *(float4*)&Zs[j * 64 + c] = v;
        }
    }

    float best[4] = {-3.4e38f, -3.4e38f, -3.4e38f, -3.4e38f};
    int   bidx[4] = {0, 0, 0, 0};

    for (int mc = 0; mc < 16; mc++) {
        __syncthreads();
        // ---- load codebook chunk transposed + duplicated:
        //      Cs2[k][2*mm] = Cs2[k][2*mm+1] = cbk[h, mc*64+mm, k] ----
        {
            int mm = tid >> 2;
            int kq = tid & 3;
            const float* src = cbk + ((h * M_ + (mc << 6) + mm) << 6) + (kq << 2);
            #pragma unroll
            for (int i = 0; i < 4; i++) {
                float4 v = *(const float4*)(src + (i << 4));
                int k0 = (kq << 2) + (i << 4);
                float2 d0 = make_float2(v.x, v.x);
                float2 d1 = make_float2(v.y, v.y);
                float2 d2 = make_float2(v.z, v.z);
                float2 d3 = make_float2(v.w, v.w);
                *(float2*)&Cs2[(k0 + 0) * 128 + 2 * mm] = d0;
                *(float2*)&Cs2[(k0 + 1) * 128 + 2 * mm] = d1;
                *(float2*)&Cs2[(k0 + 2) * 128 + 2 * mm] = d2;
                *(float2*)&Cs2[(k0 + 3) * 128 + 2 * mm] = d3;
            }
        }
        __syncthreads();

        u64 acc01[4] = {0ull, 0ull, 0ull, 0ull};   // (n0,n1) accum per m-lane j
        u64 acc23[4] = {0ull, 0ull, 0ull, 0ull};   // (n2,n3) accum per m-lane j

        const float* zp = Zs  + (tx << 2);
        const float* cp = Cs2 + (ty << 3);
        #pragma unroll 16
        for (int k = 0; k < 64; k++) {
            ulonglong2 av = *(const ulonglong2*)(zp + (k << 6));   // (n0,n1),(n2,n3)
            ulonglong2 b01 = *(const ulonglong2*)(cp + (k << 7));      // (m0,m0),(m1,m1)
            ulonglong2 b23 = *(const ulonglong2*)(cp + (k << 7) + 4);  // (m2,m2),(m3,m3)
            fma2(acc01[0], av.x, b01.x);
            fma2(acc23[0], av.y, b01.x);
            fma2(acc01[1], av.x, b01.y);
            fma2(acc23[1], av.y, b01.y);
            fma2(acc01[2], av.x, b23.x);
            fma2(acc23[2], av.y, b23.x);
            fma2(acc01[3], av.x, b23.y);
            fma2(acc23[3], av.y, b23.y);
        }

        // streaming argmax, m ascending within thread -> strict '>' keeps first idx
        int mbase = (mc << 6) + (ty << 2);
        #pragma unroll
        for (int j = 0; j < 4; j++) {
            float2 v01 = unpack2(acc01[j]);
            float2 v23 = unpack2(acc23[j]);
            int m = mbase + j;
            if (v01.x > best[0]) { best[0] = v01.x; bidx[0] = m; }
            if (v01.y > best[1]) { best[1] = v01.y; bidx[1] = m; }
            if (v23.x > best[2]) { best[2] = v23.x; bidx[2] = m; }
            if (v23.y > best[3]) { best[3] = v23.y; bidx[3] = m; }
        }
    }

    // ---- cross-ty reduction (alias Cs2) ----
    float* redV = Cs2;                   // 16*64 floats
    int*   redI = (int*)(Cs2 + 1024);    // 16*64 ints
    int*   sidx = (int*)(Cs2 + 2048);    // 64 ints
    __syncthreads();
    #pragma unroll
    for (int i = 0; i < 4; i++) {
        redV[ty * 64 + (tx << 2) + i] = best[i];
        redI[ty * 64 + (tx << 2) + i] = bidx[i];
    }
    __syncthreads();

    if (tid < 64) {
        int n = tid;
        float bv = redV[n];
        int   bi = redI[n];
        #pragma unroll
        for (int t = 1; t < 16; t++) {
            float v = redV[t * 64 + n];
            int   iv = redI[t * 64 + n];
            if (v > bv || (v == bv && iv < bi)) { bv = v; bi = iv; }
        }
        sidx[n] = bi;
        // indices_out[b, h, l]  (written as float)
        out[OUT_IDX + (b * H_ + h) * L_ + l0 + n] = (float)bi;
        atomicAdd(&g_counts[h * M_ + bi], 1.0f);
    }
    __syncthreads();

    // ---- epilogue: z_q writeback, segment sums, loss ----
    {
        int nn = tid & 63;            // column within tile
        int ks = tid >> 6;            // k-subset: handles k = ks*16 .. ks*16+15
        int ci = sidx[nn];
        const float* cw = cbk + ((h * M_ + ci) << 6);
        float* srow = &g_sums[(h * M_ + ci) << 6];
        float lsum = 0.0f;
        #pragma unroll
        for (int t = 0; t < 16; t++) {
            int k = (ks << 4) + t;
            float q  = cw[k];
            float zv = Zs[k * 64 + nn];
            float dd = zv - q;
            lsum = fmaf(dd, dd, lsum);
            out[OUT_ZQ + (b * DTOT + h * DD + k) * L_ + l0 + nn] = q;
            atomicAdd(&srow[k], zv);
        }
        #pragma unroll
        for (int o = 16; o > 0; o >>= 1)
            lsum += __shfl_down_sync(0xffffffffu, lsum, o);
        if ((tid & 31) == 0) atomicAdd(&g_loss, lsum);
    }
}

// ---------------------------------------------------------------------------
// Kernel 2: finalize — means -> slerp -> rms_norm -> new_codebooks; loss scalar
//   1024 blocks x 256 threads; one warp per (h,m) row, 2 dims per lane
// ---------------------------------------------------------------------------
__global__ __launch_bounds__(256)
void vq_final_kernel(const float* __restrict__ cbk, float* __restrict__ out) {
    const int tid  = threadIdx.x;
    const int warp = tid >> 5;
    const int lane = tid & 31;
    const int r = blockIdx.x * 8 + warp;    // row index in [0, H_*M_)
    const int j0 = lane * 2;

    if (blockIdx.x == 0 && tid == 0) {
        out[OUT_LOSS] = g_loss * (1.25f / (float)ZQ_ELEMS);
    }

    float hi0 = cbk[r * DD + j0];
    float hi1 = cbk[r * DD + j0 + 1];
    float cnt = g_counts[r];
    float* orow = out + OUT_NCB + r * DD;

    if (cnt <= 0.0f) {
        orow[j0]     = hi0;
        orow[j0 + 1] = hi1;
        return;
    }

    float inv = 1.0f / fmaxf(cnt, 1.0f);
    float lo0 = g_sums[r * DD + j0]     * inv;
    float lo1 = g_sums[r * DD + j0 + 1] * inv;

    float dot = lo0 * hi0 + lo1 * hi1;
    float nl2 = lo0 * lo0 + lo1 * lo1;
    float nh2 = hi0 * hi0 + hi1 * hi1;
    #pragma unroll
    for (int o = 16; o > 0; o >>= 1) {
        dot += __shfl_xor_sync(0xffffffffu, dot, o);
        nl2 += __shfl_xor_sync(0xffffffffu, nl2, o);
        nh2 += __shfl_xor_sync(0xffffffffu, nh2, o);
    }

    float cosv = dot / fmaxf(sqrtf(nl2) * sqrtf(nh2), COS_EPS);
    cosv = fminf(fmaxf(cosv, -1.0f + 1e-7f), 1.0f - 1e-7f);
    float omega = acosf(cosv);
    float so = sinf(omega);
    float sa = sinf((1.0f - DECAY) * omega);
    float sb = sinf(DECAY * omega);

    float o0 = (lo0 * sa + hi0 * sb) / so;
    float o1 = (lo1 * sa + hi1 * sb) / so;

    float ss = o0 * o0 + o1 * o1;
    #pragma unroll
    for (int o = 16; o > 0; o >>= 1)
        ss += __shfl_xor_sync(0xffffffffu, ss, o);

    float denom = sqrtf(ss * (1.0f / (float)DD) + EPS_RMS);
    orow[j0]     = o0 / denom;
    orow[j0 + 1] = o1 / denom;
}

// ---------------------------------------------------------------------------
extern "C" void kernel_launch(void* const* d_in, const int* in_sizes, int n_in,
                              void* d_out, int out_size) {
    const float* z   = (const float*)d_in[0];
    const float* cbk = (const float*)d_in[1];
    float* out = (float*)d_out;

    int zero_total = H_ * M_ * DD + H_ * M_ + 1;
    vq_zero_kernel<<<(zero_total + 255) / 256, 256>>>();
    vq_main_kernel<<<H_ * 256, 256>>>(z, cbk, out);
    vq_final_kernel<<<H_ * M_ / 8, 256>>>(cbk, out);
}

// round 6
// speedup vs baseline: 1.6786x; 1.6786x over previous
#include <cuda_runtime.h>
#include <cuda_bf16.h>
#include <math.h>
#include <stdint.h>

// Problem constants
#define B_   8
#define DTOT 512
#define L_   2048
#define H_   8
#define M_   1024
#define DD   64
#define N_   (B_ * L_)

// Output layout (flattened fp32 concat of (z_q, vq_loss, indices, new_codebooks))
#define OUT_ZQ   0
#define ZQ_ELEMS (B_ * DTOT * L_)
#define OUT_LOSS (ZQ_ELEMS)
#define OUT_IDX  (ZQ_ELEMS + 1)
#define IDX_ELEMS (B_ * H_ * L_)
#define OUT_NCB  (OUT_IDX + IDX_ELEMS)

#define EPS_RMS 1.1920929e-07f
#define COS_EPS 1e-8f
#define DECAY   0.99f

// ---------------- scratch ----------------------------------------------------
__device__ float g_sums[H_ * M_ * DD];
__device__ float g_counts[H_ * M_];
__device__ float g_loss;
__device__ __nv_bfloat16 g_zs0[H_ * N_ * DD];
__device__ __nv_bfloat16 g_zs1[H_ * N_ * DD];
__device__ __nv_bfloat16 g_zs2[H_ * N_ * DD];
__device__ __nv_bfloat16 g_cs0[H_ * M_ * DD];
__device__ __nv_bfloat16 g_cs1[H_ * M_ * DD];
__device__ __nv_bfloat16 g_cs2[H_ * M_ * DD];

// ---------------- smem geometry ----------------------------------------------
#define ASTRIDE_B 144                 // 64 bf16 + 8 pad = 72 elems = 144 bytes
#define SPLIT_SZ  (128 * ASTRIDE_B)   // 18432 bytes per split tile
#define SM_A      0
#define SM_B      (3 * SPLIT_SZ)      // 55296
#define SMEM_TOTAL (6 * SPLIT_SZ)     // 110592

__device__ __forceinline__ void mma_bf16(float* c, const uint32_t* a,
                                         uint32_t b0, uint32_t b1) {
    asm volatile(
        "mma.sync.aligned.m16n8k16.row.col.f32.bf16.bf16.f32 "
        "{%0,%1,%2,%3}, {%4,%5,%6,%7}, {%8,%9}, {%0,%1,%2,%3};"
        : "+f"(c[0]), "+f"(c[1]), "+f"(c[2]), "+f"(c[3])
        : "r"(a[0]), "r"(a[1]), "r"(a[2]), "r"(a[3]), "r"(b0), "r"(b1));
}

// ---------------------------------------------------------------------------
// Kernel 0: zero scratch accumulators
// ---------------------------------------------------------------------------
__global__ void vq_zero_kernel() {
    int i = blockIdx.x * blockDim.x + threadIdx.x;
    if (i < H_ * M_ * DD) g_sums[i] = 0.0f;
    int j = i - H_ * M_ * DD;
    if (j >= 0 && j < H_ * M_) g_counts[j] = 0.0f;
    if (i == H_ * M_ * DD + H_ * M_) g_loss = 0.0f;
}

// ---------------------------------------------------------------------------
// Kernel 1a: split + transpose z -> [H][N][d] bf16 triple
// ---------------------------------------------------------------------------
__global__ __launch_bounds__(256)
void vq_split_z(const float* __restrict__ z) {
    __shared__ float T[64][68];
    const int bid = blockIdx.x;
    const int h  = bid >> 8;
    const int b  = (bid >> 5) & 7;
    const int lt = bid & 31;
    const int t  = threadIdx.x;

    {
        int r = t >> 2, q = t & 3;
        const float* src = z + ((size_t)(b * DTOT + h * DD + r) * L_) + lt * 64 + q * 16;
        #pragma unroll
        for (int j = 0; j < 4; j++) {
            float4 v = *(const float4*)(src + j * 4);
            *(float4*)&T[r][q * 16 + j * 4] = v;
        }
    }
    __syncthreads();
    {
        int l = t >> 2, seg = t & 3;
        size_t obase = ((size_t)(h * N_ + b * L_ + lt * 64 + l)) * DD + seg * 16;
        uint32_t* o0 = (uint32_t*)(g_zs0 + obase);
        uint32_t* o1 = (uint32_t*)(g_zs1 + obase);
        uint32_t* o2 = (uint32_t*)(g_zs2 + obase);
        #pragma unroll
        for (int u = 0; u < 8; u++) {
            int k = seg * 16 + u * 2;
            float xa = T[k][l], xb = T[k + 1][l];
            __nv_bfloat16 a0 = __float2bfloat16(xa);
            float ra = xa - __bfloat162float(a0);
            __nv_bfloat16 a1 = __float2bfloat16(ra);
            __nv_bfloat16 a2 = __float2bfloat16(ra - __bfloat162float(a1));
            __nv_bfloat16 b0 = __float2bfloat16(xb);
            float rb = xb - __bfloat162float(b0);
            __nv_bfloat16 b1 = __float2bfloat16(rb);
            __nv_bfloat16 b2 = __float2bfloat16(rb - __bfloat162float(b1));
            o0[u] = (uint32_t)__bfloat16_as_ushort(a0) | ((uint32_t)__bfloat16_as_ushort(b0) << 16);
            o1[u] = (uint32_t)__bfloat16_as_ushort(a1) | ((uint32_t)__bfloat16_as_ushort(b1) << 16);
            o2[u] = (uint32_t)__bfloat16_as_ushort(a2) | ((uint32_t)__bfloat16_as_ushort(b2) << 16);
        }
    }
}

// ---------------------------------------------------------------------------
// Kernel 1b: split codebooks
// ---------------------------------------------------------------------------
__global__ __launch_bounds__(256)
void vq_split_c(const float* __restrict__ cbk) {
    int i = (blockIdx.x * 256 + threadIdx.x) * 4;
    #pragma unroll
    for (int j = 0; j < 4; j++) {
        float x = cbk[i + j];
        __nv_bfloat16 x0 = __float2bfloat16(x);
        float r = x - __bfloat162float(x0);
        __nv_bfloat16 x1 = __float2bfloat16(r);
        __nv_bfloat16 x2 = __float2bfloat16(r - __bfloat162float(x1));
        g_cs0[i + j] = x0;
        g_cs1[i + j] = x1;
        g_cs2[i + j] = x2;
    }
}

// ---------------------------------------------------------------------------
// Kernel 2: HMMA bf16x6 GEMM + argmax + fused epilogue
//   grid = 1024 blocks (128 rows each), 256 threads (8 warps: 4n x 2m)
// ---------------------------------------------------------------------------
__global__ __launch_bounds__(256)
void vq_mma_kernel(const float* __restrict__ z,
                   const float* __restrict__ cbk,
                   float* __restrict__ out) {
    extern __shared__ char smem[];
    char* sA = smem + SM_A;
    char* sB = smem + SM_B;

    const int tid  = threadIdx.x;
    const int wid  = tid >> 5;
    const int lane = tid & 31;
    const int g    = lane >> 2;   // groupID
    const int tg   = lane & 3;    // thread-in-group
    const int wx   = wid >> 1;    // n-warp (0..3)
    const int wy   = wid & 1;     // m-warp (0..1)

    const int blk = blockIdx.x;
    const int h  = blk >> 7;
    const int rt = blk & 127;
    const int n0 = rt << 7;
    const int b  = n0 >> 11;
    const int l0 = n0 & 2047;

    // ---- stage A (3 splits, 128 rows x 64 bf16, +8 pad) ----
    {
        const __nv_bfloat16* zsp[3] = {g_zs0, g_zs1, g_zs2};
        #pragma unroll
        for (int s = 0; s < 3; s++) {
            const __nv_bfloat16* zp = zsp[s] + (size_t)(h * N_ + n0) * DD;
            #pragma unroll
            for (int i = 0; i < 4; i++) {
                int idx = tid + i * 256;
                int row = idx >> 3, seg = idx & 7;
                uint4 v = *(const uint4*)(zp + row * DD + seg * 8);
                *(uint4*)(sA + s * SPLIT_SZ + row * ASTRIDE_B + seg * 16) = v;
            }
        }
    }

    float best[4] = {-3.4e38f, -3.4e38f, -3.4e38f, -3.4e38f};
    int   bidx[4] = {0, 0, 0, 0};

    const char* aBase = sA + (wx * 32 + g) * ASTRIDE_B + tg * 4;
    const char* bBase = sB + (wy * 64 + g) * ASTRIDE_B + tg * 4;
    const int PA[6] = {0, 0, 1, 1, 0, 2};
    const int PB[6] = {0, 1, 0, 1, 2, 0};

    for (int c = 0; c < 8; c++) {
        // ---- stage B chunk (128 codes x 64 bf16 x 3 splits) ----
        {
            const __nv_bfloat16* csp[3] = {g_cs0, g_cs1, g_cs2};
            #pragma unroll
            for (int s = 0; s < 3; s++) {
                const __nv_bfloat16* cp = csp[s] + (size_t)(h * M_ + c * 128) * DD;
                #pragma unroll
                for (int i = 0; i < 4; i++) {
                    int idx = tid + i * 256;
                    int row = idx >> 3, seg = idx & 7;
                    uint4 v = *(const uint4*)(cp + row * DD + seg * 8);
                    *(uint4*)(sB + s * SPLIT_SZ + row * ASTRIDE_B + seg * 16) = v;
                }
            }
        }
        __syncthreads();

        float acc[2][8][4] = {};
        #pragma unroll
        for (int p = 0; p < 6; p++) {
            const char* ap = aBase + PA[p] * SPLIT_SZ;
            const char* bp = bBase + PB[p] * SPLIT_SZ;
            #pragma unroll
            for (int ks = 0; ks < 4; ks++) {
                uint32_t a[2][4];
                #pragma unroll
                for (int i = 0; i < 2; i++) {
                    const char* r0 = ap + i * 16 * ASTRIDE_B + ks * 32;
                    a[i][0] = *(const uint32_t*)(r0);
                    a[i][1] = *(const uint32_t*)(r0 + 8 * ASTRIDE_B);
                    a[i][2] = *(const uint32_t*)(r0 + 16);
                    a[i][3] = *(const uint32_t*)(r0 + 8 * ASTRIDE_B + 16);
                }
                #pragma unroll
                for (int j = 0; j < 8; j++) {
                    const char* cp0 = bp + j * 8 * ASTRIDE_B + ks * 32;
                    uint32_t b0 = *(const uint32_t*)(cp0);
                    uint32_t b1 = *(const uint32_t*)(cp0 + 16);
                    mma_bf16(acc[0][j], a[0], b0, b1);
                    mma_bf16(acc[1][j], a[1], b0, b1);
                }
            }
        }

        // ---- streaming argmax (m ascending: strict '>' keeps first index) ----
        const int mchunk = c * 128 + wy * 64;
        #pragma unroll
        for (int i = 0; i < 2; i++) {
            #pragma unroll
            for (int j = 0; j < 8; j++) {
                int mb = mchunk + j * 8 + 2 * tg;
                float v0 = acc[i][j][0], v1 = acc[i][j][1];
                float v2 = acc[i][j][2], v3 = acc[i][j][3];
                int r0 = i * 2, r1 = i * 2 + 1;
                if (v0 > best[r0]) { best[r0] = v0; bidx[r0] = mb; }
                if (v1 > best[r0]) { best[r0] = v1; bidx[r0] = mb + 1; }
                if (v2 > best[r1]) { best[r1] = v2; bidx[r1] = mb; }
                if (v3 > best[r1]) { best[r1] = v3; bidx[r1] = mb + 1; }
            }
        }
        __syncthreads();   // all warps done reading B before next chunk load
    }

    // ---- cross-lane reduce (lanes differing in tg hold same rows) ----
    #pragma unroll
    for (int r = 0; r < 4; r++) {
        #pragma unroll
        for (int o = 1; o < 4; o <<= 1) {
            float ov = __shfl_xor_sync(0xffffffffu, best[r], o);
            int   oi = __shfl_xor_sync(0xffffffffu, bidx[r], o);
            if (ov > best[r] || (ov == best[r] && oi < bidx[r])) {
                best[r] = ov; bidx[r] = oi;
            }
        }
    }

    // ---- cross-warp (wy) reduce via smem (B region is free now) ----
    float* rV   = (float*)sB;            // 256 floats
    int*   rI   = (int*)(sB + 1024);     // 256 ints
    int*   sidx = (int*)(sB + 2048);     // 128 ints
    if (tg == 0) {
        #pragma unroll
        for (int r = 0; r < 4; r++) {
            int lrow = wx * 32 + (r >> 1) * 16 + g + (r & 1) * 8;
            rV[wy * 128 + lrow] = best[r];
            rI[wy * 128 + lrow] = bidx[r];
        }
    }
    __syncthreads();

    if (tid < 128) {
        float v0 = rV[tid];       int i0 = rI[tid];
        float v1 = rV[128 + tid]; int i1 = rI[128 + tid];
        if (v1 > v0 || (v1 == v0 && i1 < i0)) { v0 = v1; i0 = i1; }
        sidx[tid] = i0;
        out[OUT_IDX + (b * H_ + h) * L_ + l0 + tid] = (float)i0;
        atomicAdd(&g_counts[h * M_ + i0], 1.0f);
    }
    __syncthreads();

    // ---- epilogue: 2 threads per row, 32 k each ----
    {
        const int nn = tid & 127;
        const int kh = tid >> 7;
        const int ci = sidx[nn];
        const int l  = l0 + nn;
        const float* cw  = cbk + (size_t)(h * M_ + ci) * DD + kh * 32;
        float* srow      = g_sums + (size_t)(h * M_ + ci) * DD + kh * 32;
        const float* zsr = z   + (size_t)(b * DTOT + h * DD + kh * 32) * L_ + l;
        float* zqd       = out + OUT_ZQ + (size_t)(b * DTOT + h * DD + kh * 32) * L_ + l;
        float lsum = 0.0f;
        #pragma unroll 8
        for (int k = 0; k < 32; k++) {
            float q  = cw[k];
            float zv = zsr[(size_t)k * L_];
            float dd = zv - q;
            lsum = fmaf(dd, dd, lsum);
            zqd[(size_t)k * L_] = q;
            atomicAdd(&srow[k], zv);
        }
        #pragma unroll
        for (int o = 16; o > 0; o >>= 1)
            lsum += __shfl_down_sync(0xffffffffu, lsum, o);
        if ((tid & 31) == 0) atomicAdd(&g_loss, lsum);
    }
}

// ---------------------------------------------------------------------------
// Kernel 3: finalize — means -> slerp -> rms_norm -> new_codebooks; loss
// ---------------------------------------------------------------------------
__global__ __launch_bounds__(256)
void vq_final_kernel(const float* __restrict__ cbk, float* __restrict__ out) {
    const int tid  = threadIdx.x;
    const int warp = tid >> 5;
    const int lane = tid & 31;
    const int r = blockIdx.x * 8 + warp;
    const int j0 = lane * 2;

    if (blockIdx.x == 0 && tid == 0) {
        out[OUT_LOSS] = g_loss * (1.25f / (float)ZQ_ELEMS);
    }

    float hi0 = cbk[r * DD + j0];
    float hi1 = cbk[r * DD + j0 + 1];
    float cnt = g_counts[r];
    float* orow = out + OUT_NCB + r * DD;

    if (cnt <= 0.0f) {
        orow[j0]     = hi0;
        orow[j0 + 1] = hi1;
        return;
    }

    float inv = 1.0f / fmaxf(cnt, 1.0f);
    float lo0 = g_sums[r * DD + j0]     * inv;
    float lo1 = g_sums[r * DD + j0 + 1] * inv;

    float dot = lo0 * hi0 + lo1 * hi1;
    float nl2 = lo0 * lo0 + lo1 * lo1;
    float nh2 = hi0 * hi0 + hi1 * hi1;
    #pragma unroll
    for (int o = 16; o > 0; o >>= 1) {
        dot += __shfl_xor_sync(0xffffffffu, dot, o);
        nl2 += __shfl_xor_sync(0xffffffffu, nl2, o);
        nh2 += __shfl_xor_sync(0xffffffffu, nh2, o);
    }

    float cosv = dot / fmaxf(sqrtf(nl2) * sqrtf(nh2), COS_EPS);
    cosv = fminf(fmaxf(cosv, -1.0f + 1e-7f), 1.0f - 1e-7f);
    float omega = acosf(cosv);
    float so = sinf(omega);
    float sa = sinf((1.0f - DECAY) * omega);
    float sb = sinf(DECAY * omega);

    float o0 = (lo0 * sa + hi0 * sb) / so;
    float o1 = (lo1 * sa + hi1 * sb) / so;

    float ss = o0 * o0 + o1 * o1;
    #pragma unroll
    for (int o = 16; o > 0; o >>= 1)
        ss += __shfl_xor_sync(0xffffffffu, ss, o);

    float denom = sqrtf(ss * (1.0f / (float)DD) + EPS_RMS);
    orow[j0]     = o0 / denom;
    orow[j0 + 1] = o1 / denom;
}

// ---------------------------------------------------------------------------
extern "C" void kernel_launch(void* const* d_in, const int* in_sizes, int n_in,
                              void* d_out, int out_size) {
    const float* z   = (const float*)d_in[0];
    const float* cbk = (const float*)d_in[1];
    float* out = (float*)d_out;

    cudaFuncSetAttribute(vq_mma_kernel, cudaFuncAttributeMaxDynamicSharedMemorySize,
                         SMEM_TOTAL);

    int zero_total = H_ * M_ * DD + H_ * M_ + 1;
    vq_zero_kernel<<<(zero_total + 255) / 256, 256>>>();
    vq_split_z<<<H_ * B_ * (L_ / 64), 256>>>(z);
    vq_split_c<<<(H_ * M_ * DD) / (256 * 4), 256>>>(cbk);
    vq_mma_kernel<<<H_ * 128, 256, SMEM_TOTAL>>>(z, cbk, out);
    vq_final_kernel<<<H_ * M_ / 8, 256>>>(cbk, out);
}